// round 17
// baseline (speedup 1.0000x reference)
#include <cuda_runtime.h>
#include <cuda_bf16.h>
#include <math.h>

// Problem constants
#define Bsz     2
#define Npts    8192
#define Kn      3
#define NQ      (Bsz * Npts)
#define THREADS 256
#define G       4                    // queries per warp
#define QPB     16                   // 4 query-groups x G -> 1024 blocks
#define TILE_C  1024                 // candidates per smem tile (per half)
#define NPAIRS  4                    // tile pairs: lo tiles 0..3, hi tiles 4..7
#define HALF_N  (Npts / 2)           // 4096 candidates per half

#define FULLMASK 0xffffffffu

// Precomputed candidate vectors {-2x, -2y, -2z, |s|^2}
__device__ float4 g_c4[NQ];

// Top-3 insert, strict < in ascending candidate order (= top_k tie-break).
__device__ __forceinline__ void insert3(float f, int cand,
                                        float& t0, float& t1, float& t2,
                                        int& i0, int& i1, int& i2)
{
    if (f < t2) {
        if (f < t0)      { t2 = t1; i2 = i1; t1 = t0; i1 = i0; t0 = f; i0 = cand; }
        else if (f < t1) { t2 = t1; i2 = i1; t1 = f;  i1 = cand; }
        else             { t2 = f;  i2 = cand; }
    }
}

// Prep: build g_c4 and zero the output accumulator.
__global__ void prep_kernel(const float* __restrict__ xyz, float* __restrict__ out)
{
    const int t = blockIdx.x * blockDim.x + threadIdx.x;
    if (t == 0) out[0] = 0.0f;
    if (t >= NQ) return;
    const float x = xyz[t * 3 + 0];
    const float y = xyz[t * 3 + 1];
    const float z = xyz[t * 3 + 2];
    const float n = fmaf(x, x, fmaf(y, y, z * z));
    g_c4[t] = make_float4(-2.0f * x, -2.0f * y, -2.0f * z, n);
}

// Ballot-gated insert of a 32-candidate window for one query.
__device__ __forceinline__ void process_window(float tg, int cbase,
                                               float& t0, float& t1, float& t2,
                                               int& i0, int& i1, int& i2)
{
    unsigned bg = __ballot_sync(FULLMASK, tg < t2);
    while (bg) {
        const int l = __ffs(bg) - 1;
        bg &= bg - 1;
        const float tv = __shfl_sync(FULLMASK, tg, l);
        insert3(tv, cbase + l, t0, t1, t2, i0, i1, i2);
    }
}

// ---------------------------------------------------------------------------
// Fused KNN + loss, split-range warp pairs. 8 warps/block; warp w and w+4
// own the SAME G=4 queries but scan disjoint candidate halves (lo: 0..4095,
// hi: 4096..8191). Per-pair cost identical to the proven R14 64-wide scan;
// total warps double (55/SM) for latency hiding. End merge: hi warp's top-3
// (ascending t, index-correct internally) strict-< inserted into lo warp's
// state -> lo wins ties (indices strictly smaller) == sequential strict-<
// over the full range (jax top_k tie-break preserved).
// ---------------------------------------------------------------------------
__global__ __launch_bounds__(THREADS) void knnreg_kernel(
    const float* __restrict__ xyz,   // [B,N,3]
    const float* __restrict__ rot,   // [B,N,4]
    const float* __restrict__ scl,   // [B,N,3]
    const float* __restrict__ col,   // [B,N,45]
    const float* __restrict__ opa,   // [B,N,1]
    float* __restrict__ out)
{
    const int tid   = threadIdx.x;
    const int lane  = tid & 31;
    const int wid   = tid >> 5;          // 0..7
    const int grp   = wid & 3;           // query group 0..3
    const int half  = wid >> 2;          // 0 = lo candidates, 1 = hi
    const int qblk  = blockIdx.x * QPB;
    const int b     = qblk >> 13;        // QPB=16 | 8192
    const float* xb = xyz + (size_t)b * Npts * 3;
    const float4* cb4 = g_c4 + (size_t)b * Npts;
    const int qw    = (qblk & (Npts - 1)) + grp * G;

    // Warp's queries (broadcast loads)
    float qx[G], qy[G], qz[G], qn[G];
    #pragma unroll
    for (int g = 0; g < G; g++) {
        const int q = qw + g;
        qx[g] = xb[q * 3 + 0];
        qy[g] = xb[q * 3 + 1];
        qz[g] = xb[q * 3 + 2];
        qn[g] = fmaf(qx[g], qx[g], fmaf(qy[g], qy[g], qz[g] * qz[g]));
    }

    float t0[G], t1[G], t2[G];
    int   i0[G], i1[G], i2[G];

    __shared__ float4 scLo[TILE_C];
    __shared__ float4 scHi[TILE_C];
    __shared__ float  mT[4][G * Kn];
    __shared__ int    mI[4][G * Kn];
    __shared__ float  red[4];

    const float4* my  = half ? scHi : scLo;
    const int rbase   = half * HALF_N;    // 0 or 4096: warp's range offset

    // ---- tile-pair loop ----
    for (int tp = 0; tp < NPAIRS; tp++) {
        if (tp > 0) __syncthreads();      // prior scan done before overwrite
        // stage lo tile tp and hi tile tp+4
        {
            const int lb = tp * TILE_C;
            const int hb = (tp + NPAIRS) * TILE_C;
            for (int k = tid; k < TILE_C; k += THREADS) {
                scLo[k] = cb4[lb + k];
                scHi[k] = cb4[hb + k];
            }
        }
        __syncthreads();

        int sbeg = 0;
        if (tp == 0) {
            // prologue: warp's first 32 candidates via lex-argmin (exact)
            const float4 c = my[lane];
            #pragma unroll
            for (int g = 0; g < G; g++) {
                float t = fmaf(qx[g], c.x, c.w);
                t = fmaf(qy[g], c.y, t);
                t = fmaf(qz[g], c.z, t);
                float v = t; int iv = rbase + lane;
                float rt[Kn]; int ri[Kn];
                #pragma unroll
                for (int r = 0; r < Kn; r++) {
                    float bv = v; int bi = iv;
                    #pragma unroll
                    for (int off = 16; off > 0; off >>= 1) {
                        const float ov = __shfl_xor_sync(FULLMASK, bv, off);
                        const int   oo = __shfl_xor_sync(FULLMASK, bi, off);
                        if (ov < bv || (ov == bv && oo < bi)) { bv = ov; bi = oo; }
                    }
                    rt[r] = bv; ri[r] = bi;
                    if (iv == bi) v = INFINITY;
                }
                t0[g] = rt[0]; t1[g] = rt[1]; t2[g] = rt[2];
                i0[g] = ri[0]; i1[g] = ri[1]; i2[g] = ri[2];
            }
            // candidates 32..63 of own range (single-width step)
            {
                const float4 c2 = my[32 + lane];
                float tg[G];
                #pragma unroll
                for (int g = 0; g < G; g++) {
                    float t = fmaf(qx[g], c2.x, c2.w);
                    t = fmaf(qy[g], c2.y, t);
                    tg[g] = fmaf(qz[g], c2.z, t);
                }
                const bool p = (tg[0] < t2[0]) | (tg[1] < t2[1])
                             | (tg[2] < t2[2]) | (tg[3] < t2[3]);
                if (__ballot_sync(FULLMASK, p)) {
                    #pragma unroll
                    for (int g = 0; g < G; g++)
                        process_window(tg[g], rbase + 32,
                                       t0[g], t1[g], t2[g], i0[g], i1[g], i2[g]);
                }
            }
            sbeg = 64;
        }

        // main scan: 64 candidates per step over own tile
        const int tbase = rbase + tp * TILE_C;
        for (int s = sbeg; s < TILE_C; s += 64) {
            const float4 ca = my[s + lane];
            const float4 cb = my[s + 32 + lane];
            float ta[G], tb[G];
            #pragma unroll
            for (int g = 0; g < G; g++) {
                float t = fmaf(qx[g], ca.x, ca.w);
                t = fmaf(qy[g], ca.y, t);
                ta[g] = fmaf(qz[g], ca.z, t);
                float u = fmaf(qx[g], cb.x, cb.w);
                u = fmaf(qy[g], cb.y, u);
                tb[g] = fmaf(qz[g], cb.z, u);
            }
            const bool p = (ta[0] < t2[0]) | (ta[1] < t2[1])
                         | (ta[2] < t2[2]) | (ta[3] < t2[3])
                         | (tb[0] < t2[0]) | (tb[1] < t2[1])
                         | (tb[2] < t2[2]) | (tb[3] < t2[3]);
            if (__ballot_sync(FULLMASK, p)) {
                const int cbd = tbase + s;
                #pragma unroll
                for (int g = 0; g < G; g++) {
                    process_window(ta[g], cbd,      t0[g], t1[g], t2[g], i0[g], i1[g], i2[g]);
                    process_window(tb[g], cbd + 32, t0[g], t1[g], t2[g], i0[g], i1[g], i2[g]);
                }
            }
        }
    }

    // ---- merge: hi warp publishes its top-3; lo warp strict-< inserts ----
    if (half == 1 && lane == 0) {
        #pragma unroll
        for (int g = 0; g < G; g++) {
            mT[grp][g * Kn + 0] = t0[g]; mI[grp][g * Kn + 0] = i0[g];
            mT[grp][g * Kn + 1] = t1[g]; mI[grp][g * Kn + 1] = i1[g];
            mT[grp][g * Kn + 2] = t2[g]; mI[grp][g * Kn + 2] = i2[g];
        }
    }
    __syncthreads();

    if (half == 0) {
        #pragma unroll
        for (int g = 0; g < G; g++) {
            #pragma unroll
            for (int r = 0; r < Kn; r++) {
                // ascending t within hi set; strict < -> lo wins ties (lower idx)
                insert3(mT[grp][g * Kn + r], mI[grp][g * Kn + r],
                        t0[g], t1[g], t2[g], i0[g], i1[g], i2[g]);
            }
        }

        // ---- fused loss phase (lo warps only) ----
        float local = 0.0f;

        #pragma unroll
        for (int g = 0; g < G; g++) {
            if (lane == 0) {
                local += ((t0[g] + qn[g]) + (t1[g] + qn[g]) + (t2[g] + qn[g]))
                         * (1.0f / ((float)Bsz * Npts * Kn));
            }

            const int r0 = b * Npts + i0[g];
            const int r1 = b * Npts + i1[g];
            const int r2 = b * Npts + i2[g];

            // 53 channels: 0..3 rot(4), 4..6 scales(3), 7 opacity(1), 8..52 colors(45)
            for (int c = lane; c < 53; c += 32) {
                const float* bp; int C; int cc;
                if (c < 4)       { bp = rot; C = 4;  cc = c;     }
                else if (c < 7)  { bp = scl; C = 3;  cc = c - 4; }
                else if (c < 8)  { bp = opa; C = 1;  cc = 0;     }
                else             { bp = col; C = 45; cc = c - 8; }

                const float x0 = __ldg(bp + (size_t)r0 * C + cc);
                const float x1 = __ldg(bp + (size_t)r1 * C + cc);
                const float x2 = __ldg(bp + (size_t)r2 * C + cc);

                const float m  = (x0 + x1 + x2) * (1.0f / 3.0f);
                const float e0 = x0 - m, e1 = x1 - m, e2 = x2 - m;
                const float var = fmaf(e0, e0, fmaf(e1, e1, e2 * e2)) * 0.5f; // ddof=1
                local += sqrtf(var) * (1.0f / ((float)Bsz * Npts * (float)C));
            }
        }

        // warp reduce
        #pragma unroll
        for (int off = 16; off > 0; off >>= 1)
            local += __shfl_xor_sync(FULLMASK, local, off);

        if (lane == 0) red[grp] = local;
    }
    __syncthreads();

    if (tid == 0) {
        float s = red[0] + red[1] + red[2] + red[3];
        atomicAdd(out, s);
    }
}

// ---------------------------------------------------------------------------
extern "C" void kernel_launch(void* const* d_in, const int* in_sizes, int n_in,
                              void* d_out, int out_size)
{
    const float* xyz = (const float*)d_in[0];
    const float* rot = (const float*)d_in[1];
    const float* scl = (const float*)d_in[2];
    const float* col = (const float*)d_in[3];
    const float* opa = (const float*)d_in[4];
    float* out = (float*)d_out;

    prep_kernel<<<NQ / 256, 256>>>(xyz, out);
    knnreg_kernel<<<NQ / QPB, THREADS>>>(xyz, rot, scl, col, opa, out);
}